// round 1
// baseline (speedup 1.0000x reference)
#include <cuda_runtime.h>
#include <cuda_bf16.h>
#include <cstdint>
#include <cstddef>

// ---------------------------------------------------------------------------
// Problem constants
// ---------------------------------------------------------------------------
#define N_CODES 4880
#define T_STEPS 4096
#define VDIM    512
#define HD      512
#define G3      1536   // 3*HD

// ---------------------------------------------------------------------------
// Scratch (device globals — no allocation allowed)
// ---------------------------------------------------------------------------
__device__ float g_visit[(size_t)T_STEPS * VDIM];     // 8 MB
__device__ float g_gi[(size_t)T_STEPS * G3];          // 24 MB
__device__ float g_hs[(size_t)T_STEPS * HD];          // 8 MB
__device__ float g_logits[T_STEPS];
__device__ float g_alpha[T_STEPS];
__device__ float g_part[32 * HD];

// ---------------------------------------------------------------------------
// Helpers
// ---------------------------------------------------------------------------
__device__ __forceinline__ unsigned smem_u32(const void* p) {
    unsigned a;
    asm("{ .reg .u64 t; cvta.to.shared.u64 t, %1; cvt.u32.u64 %0, t; }"
        : "=r"(a) : "l"(p));
    return a;
}

__device__ __forceinline__ void cluster_sync_all() {
    asm volatile("barrier.cluster.arrive.aligned;" ::: "memory");
    asm volatile("barrier.cluster.wait.aligned;" ::: "memory");
}

// ---------------------------------------------------------------------------
// GEMM1: visit[t][d] = sum_k H[k][t] * X[k][d]
//   t: 4096 (BM=128), d: 512 (BN=64), k: 4880 (BK=16)
//   256 threads, 8x4 register tile per thread
// ---------------------------------------------------------------------------
__global__ void __launch_bounds__(256)
gemm1_kernel(const float* __restrict__ H, const float* __restrict__ X)
{
    __shared__ float As[16 * 128];  // [kk][tt]
    __shared__ float Bs[16 * 64];   // [kk][dd]
    const int tid = threadIdx.x;
    const int t0 = blockIdx.x * 128;
    const int d0 = blockIdx.y * 64;
    const int tx = tid & 15;        // -> d
    const int ty = tid >> 4;        // -> t

    float acc[8][4];
#pragma unroll
    for (int m = 0; m < 8; m++)
#pragma unroll
        for (int n = 0; n < 4; n++) acc[m][n] = 0.0f;

    for (int k0 = 0; k0 < N_CODES; k0 += 16) {
        // load A tile: 16x128 floats = 512 float4; contiguous along t
#pragma unroll
        for (int j = 0; j < 2; j++) {
            int idx = tid + (j << 8);
            int kk  = idx >> 5;             // 0..15
            int tt4 = (idx & 31) << 2;      // 0..124
            float4 v = *(const float4*)(H + (size_t)(k0 + kk) * T_STEPS + t0 + tt4);
            *(float4*)(As + (kk << 7) + tt4) = v;
        }
        // load B tile: 16x64 floats = 256 float4; contiguous along d
        {
            int kk  = tid >> 4;
            int dd4 = (tid & 15) << 2;
            float4 v = *(const float4*)(X + (size_t)(k0 + kk) * VDIM + d0 + dd4);
            *(float4*)(Bs + (kk << 6) + dd4) = v;
        }
        __syncthreads();
#pragma unroll
        for (int kk = 0; kk < 16; kk++) {
            float4 a0 = *(const float4*)(As + (kk << 7) + (ty << 3));
            float4 a1 = *(const float4*)(As + (kk << 7) + (ty << 3) + 4);
            float4 b  = *(const float4*)(Bs + (kk << 6) + (tx << 2));
            float a[8] = {a0.x, a0.y, a0.z, a0.w, a1.x, a1.y, a1.z, a1.w};
            float bb[4] = {b.x, b.y, b.z, b.w};
#pragma unroll
            for (int m = 0; m < 8; m++)
#pragma unroll
                for (int n = 0; n < 4; n++)
                    acc[m][n] += a[m] * bb[n];
        }
        __syncthreads();
    }
#pragma unroll
    for (int m = 0; m < 8; m++) {
        float4 v = make_float4(acc[m][0], acc[m][1], acc[m][2], acc[m][3]);
        *(float4*)(g_visit + (size_t)(t0 + (ty << 3) + m) * VDIM + d0 + (tx << 2)) = v;
    }
}

// ---------------------------------------------------------------------------
// GEMM2: gi[t][g] = b_ih[g] + sum_d visit[t][d] * W_ih[g][d]
//   t: 4096 (BM=128), g: 1536 (BN=64), d: 512 (BK=16)
// ---------------------------------------------------------------------------
__global__ void __launch_bounds__(256)
gemm2_kernel(const float* __restrict__ Wih, const float* __restrict__ bih)
{
    __shared__ float As[16 * 128];  // [kk][tt]
    __shared__ float Bs[16 * 64];   // [kk][gg]
    const int tid = threadIdx.x;
    const int t0 = blockIdx.x * 128;
    const int g0 = blockIdx.y * 64;
    const int tx = tid & 15;
    const int ty = tid >> 4;

    float acc[8][4];
#pragma unroll
    for (int m = 0; m < 8; m++)
#pragma unroll
        for (int n = 0; n < 4; n++) acc[m][n] = 0.0f;

    for (int k0 = 0; k0 < VDIM; k0 += 16) {
        // A: visit rows (k-contiguous) -> transpose into As[kk][tt]
#pragma unroll
        for (int j = 0; j < 2; j++) {
            int idx = tid + (j << 8);        // 0..511
            int tt  = idx >> 2;              // 0..127
            int kk  = (idx & 3) << 2;        // 0,4,8,12
            float4 v = *(const float4*)(g_visit + (size_t)(t0 + tt) * VDIM + k0 + kk);
            As[(kk + 0) * 128 + tt] = v.x;
            As[(kk + 1) * 128 + tt] = v.y;
            As[(kk + 2) * 128 + tt] = v.z;
            As[(kk + 3) * 128 + tt] = v.w;
        }
        // B: W_ih rows (k-contiguous) -> transpose into Bs[kk][gg]
        {
            int gg = tid >> 2;               // 0..63
            int kk = (tid & 3) << 2;
            float4 v = *(const float4*)(Wih + (size_t)(g0 + gg) * VDIM + k0 + kk);
            Bs[(kk + 0) * 64 + gg] = v.x;
            Bs[(kk + 1) * 64 + gg] = v.y;
            Bs[(kk + 2) * 64 + gg] = v.z;
            Bs[(kk + 3) * 64 + gg] = v.w;
        }
        __syncthreads();
#pragma unroll
        for (int kk = 0; kk < 16; kk++) {
            float4 a0 = *(const float4*)(As + (kk << 7) + (ty << 3));
            float4 a1 = *(const float4*)(As + (kk << 7) + (ty << 3) + 4);
            float4 b  = *(const float4*)(Bs + (kk << 6) + (tx << 2));
            float a[8] = {a0.x, a0.y, a0.z, a0.w, a1.x, a1.y, a1.z, a1.w};
            float bb[4] = {b.x, b.y, b.z, b.w};
#pragma unroll
            for (int m = 0; m < 8; m++)
#pragma unroll
                for (int n = 0; n < 4; n++)
                    acc[m][n] += a[m] * bb[n];
        }
        __syncthreads();
    }
    float4 bv = *(const float4*)(bih + g0 + (tx << 2));
#pragma unroll
    for (int m = 0; m < 8; m++) {
        float4 v = make_float4(acc[m][0] + bv.x, acc[m][1] + bv.y,
                               acc[m][2] + bv.z, acc[m][3] + bv.w);
        *(float4*)(g_gi + (size_t)(t0 + (ty << 3) + m) * G3 + g0 + (tx << 2)) = v;
    }
}

// ---------------------------------------------------------------------------
// GRU scan: 16-CTA cluster, persistent. CTA c owns hidden units [32c, 32c+32)
// across all 3 gates -> 96 W_hh rows. Local row r (0..95): gate = r/32,
// unit u = r%32, global gate row = gate*512 + c*32 + u.
// Warp w (0..15) computes rows [6w, 6w+6): rows 0..3 from registers,
// rows 4..5 from shared memory. h broadcast to peers via st.shared::cluster,
// one barrier.cluster per step.
// ---------------------------------------------------------------------------
#define SCAN_THREADS 512
#define SCAN_SMEM_FLOATS (16384 + 1024 + 96 + 96)
#define SCAN_SMEM_BYTES  (SCAN_SMEM_FLOATS * 4)

__global__ void __launch_bounds__(SCAN_THREADS, 1)
scan_kernel(const float* __restrict__ Whh, const float* __restrict__ bhh)
{
    extern __shared__ float sm[];
    float* Wsh = sm;                     // [16 warps][2 rows][512] = 16384
    float* hb  = sm + 16384;             // [2][512]
    float* pre = sm + 16384 + 1024;      // [96]
    float* bsh = pre + 96;               // [96]

    const int tid  = threadIdx.x;
    const int lane = tid & 31;
    const int w    = tid >> 5;           // 0..15
    const int cta  = blockIdx.x;         // == cluster rank (grid == cluster)

    // --- one-time weight staging ---
    float4 wreg[4][4];
#pragma unroll
    for (int i = 0; i < 4; i++) {
        int r = w * 6 + i;
        int grow = ((r >> 5) << 9) + (cta << 5) + (r & 31);
        const float* src = Whh + (size_t)grow * HD + (lane << 2);
#pragma unroll
        for (int k = 0; k < 4; k++)
            wreg[i][k] = *(const float4*)(src + (k << 7));
    }
    for (int i = 4; i < 6; i++) {
        int r = w * 6 + i;
        int grow = ((r >> 5) << 9) + (cta << 5) + (r & 31);
        const float* src = Whh + (size_t)grow * HD + (lane << 2);
        float* dst = Wsh + ((w * 2 + (i - 4)) << 9) + (lane << 2);
#pragma unroll
        for (int k = 0; k < 4; k++)
            *(float4*)(dst + (k << 7)) = *(const float4*)(src + (k << 7));
    }
    if (tid < 96) {
        int r = tid;
        int grow = ((r >> 5) << 9) + (cta << 5) + (r & 31);
        bsh[r] = bhh[grow];
    }
    if (tid < HD) hb[tid] = 0.0f;   // h_0 = 0
    __syncthreads();
    cluster_sync_all();

    for (int t = 0; t < T_STEPS; t++) {
        const int cur = t & 1, nxt = cur ^ 1;
        const float* hcur = hb + (cur << 9);

        // prefetch gi triple + h_old for the gate phase (warp 0 = gate warp)
        float gir = 0.f, giz = 0.f, gin = 0.f, hold = 0.f;
        if (w == 0) {
            int j = (cta << 5) + lane;
            const float* gp = g_gi + (size_t)t * G3 + j;
            gir  = __ldg(gp);
            giz  = __ldg(gp + HD);
            gin  = __ldg(gp + 2 * HD);
            hold = hcur[j];
        }

        // h slice for this lane: columns 4*lane + 128*k .. +4
        float4 h4[4];
#pragma unroll
        for (int k = 0; k < 4; k++)
            h4[k] = *(const float4*)(hcur + (lane << 2) + (k << 7));

        float accs[6];
#pragma unroll
        for (int i = 0; i < 4; i++) {
            float s = 0.f;
#pragma unroll
            for (int k = 0; k < 4; k++) {
                s += wreg[i][k].x * h4[k].x;
                s += wreg[i][k].y * h4[k].y;
                s += wreg[i][k].z * h4[k].z;
                s += wreg[i][k].w * h4[k].w;
            }
            accs[i] = s;
        }
#pragma unroll
        for (int i = 4; i < 6; i++) {
            const float* wp = Wsh + ((w * 2 + (i - 4)) << 9) + (lane << 2);
            float s = 0.f;
#pragma unroll
            for (int k = 0; k < 4; k++) {
                float4 w4 = *(const float4*)(wp + (k << 7));
                s += w4.x * h4[k].x + w4.y * h4[k].y + w4.z * h4[k].z + w4.w * h4[k].w;
            }
            accs[i] = s;
        }
#pragma unroll
        for (int i = 0; i < 6; i++) {
            float s = accs[i];
            s += __shfl_xor_sync(0xffffffffu, s, 16);
            s += __shfl_xor_sync(0xffffffffu, s, 8);
            s += __shfl_xor_sync(0xffffffffu, s, 4);
            s += __shfl_xor_sync(0xffffffffu, s, 2);
            s += __shfl_xor_sync(0xffffffffu, s, 1);
            if (lane == i) pre[w * 6 + i] = s + bsh[w * 6 + i];
        }
        __syncthreads();

        // gate math for our 32 hidden units (warp 0)
        if (w == 0) {
            int u = lane;
            float hr = pre[u];
            float hz = pre[32 + u];
            float hn = pre[64 + u];
            float rg = 1.0f / (1.0f + __expf(-(gir + hr)));
            float zg = 1.0f / (1.0f + __expf(-(giz + hz)));
            float ng = tanhf(gin + rg * hn);
            float hnew = (1.0f - zg) * ng + zg * hold;
            hb[(nxt << 9) + (cta << 5) + u] = hnew;       // local copy
            g_hs[(size_t)t * HD + (cta << 5) + u] = hnew; // record for attention
        }
        __syncthreads();

        // broadcast our 32-unit chunk: warp w pushes to peer CTA w
        {
            float v = hb[(nxt << 9) + (cta << 5) + lane];
            if (w != cta) {
                unsigned laddr = smem_u32(&hb[(nxt << 9) + (cta << 5) + lane]);
                asm volatile(
                    "{ .reg .u32 ra; mapa.shared::cluster.u32 ra, %0, %1; "
                    "st.shared::cluster.f32 [ra], %2; }"
                    :: "r"(laddr), "r"(w), "f"(v));
            }
        }
        cluster_sync_all();   // arrive releases the DSMEM stores
    }
}

// ---------------------------------------------------------------------------
// Attention pooling
// ---------------------------------------------------------------------------
__global__ void __launch_bounds__(128)
att_logits_kernel(const float* __restrict__ watt)
{
    int w = blockIdx.x * 4 + (threadIdx.x >> 5);   // 0..511
    int lane = threadIdx.x & 31;
    for (int i = 0; i < 8; i++) {
        int t = w * 8 + i;
        const float* hp = g_hs + (size_t)t * HD;
        float acc = 0.f;
#pragma unroll
        for (int k = 0; k < 16; k++)
            acc += hp[lane + (k << 5)] * watt[lane + (k << 5)];
        acc += __shfl_xor_sync(0xffffffffu, acc, 16);
        acc += __shfl_xor_sync(0xffffffffu, acc, 8);
        acc += __shfl_xor_sync(0xffffffffu, acc, 4);
        acc += __shfl_xor_sync(0xffffffffu, acc, 2);
        acc += __shfl_xor_sync(0xffffffffu, acc, 1);
        if (lane == 0) g_logits[t] = acc;
    }
}

__global__ void __launch_bounds__(1024)
att_softmax_kernel()
{
    __shared__ float red[1024];
    int tid = threadIdx.x;
    float l[4];
    float mx = -1e30f;
#pragma unroll
    for (int i = 0; i < 4; i++) {
        l[i] = g_logits[tid + (i << 10)];
        mx = fmaxf(mx, l[i]);
    }
    red[tid] = mx;
    __syncthreads();
    for (int s = 512; s > 0; s >>= 1) {
        if (tid < s) red[tid] = fmaxf(red[tid], red[tid + s]);
        __syncthreads();
    }
    mx = red[0];
    __syncthreads();
    float e[4];
    float se = 0.f;
#pragma unroll
    for (int i = 0; i < 4; i++) {
        e[i] = __expf(l[i] - mx);
        se += e[i];
    }
    red[tid] = se;
    __syncthreads();
    for (int s = 512; s > 0; s >>= 1) {
        if (tid < s) red[tid] += red[tid + s];
        __syncthreads();
    }
    float inv = 1.0f / red[0];
#pragma unroll
    for (int i = 0; i < 4; i++)
        g_alpha[tid + (i << 10)] = e[i] * inv;
}

__global__ void __launch_bounds__(512)
att_out_kernel()
{
    int b = blockIdx.x;     // 0..31
    int d = threadIdx.x;    // 0..511
    float acc = 0.f;
    for (int i = 0; i < 128; i++) {
        int t = b * 128 + i;
        acc += g_alpha[t] * g_hs[(size_t)t * HD + d];
    }
    g_part[b * HD + d] = acc;
}

__global__ void __launch_bounds__(512)
att_final_kernel(float* __restrict__ out)
{
    int d = threadIdx.x;
    float acc = 0.f;
#pragma unroll
    for (int b = 0; b < 32; b++)
        acc += g_part[b * HD + d];
    out[d] = acc;
}

// ---------------------------------------------------------------------------
// Launch
// ---------------------------------------------------------------------------
extern "C" void kernel_launch(void* const* d_in, const int* in_sizes, int n_in,
                              void* d_out, int out_size)
{
    const float* H    = (const float*)d_in[0];
    // d_in[1] = TE (unused by reference)
    const float* X    = (const float*)d_in[2];
    const float* Wih  = (const float*)d_in[3];
    const float* Whh  = (const float*)d_in[4];
    const float* bih  = (const float*)d_in[5];
    const float* bhh  = (const float*)d_in[6];
    const float* watt = (const float*)d_in[7];
    float* out = (float*)d_out;

    gemm1_kernel<<<dim3(32, 8), 256>>>(H, X);
    gemm2_kernel<<<dim3(32, 24), 256>>>(Wih, bih);

    cudaFuncSetAttribute(scan_kernel,
                         cudaFuncAttributeMaxDynamicSharedMemorySize,
                         SCAN_SMEM_BYTES);
    cudaFuncSetAttribute(scan_kernel,
                         cudaFuncAttributeNonPortableClusterSizeAllowed, 1);

    cudaLaunchConfig_t cfg = {};
    cfg.gridDim = dim3(16, 1, 1);
    cfg.blockDim = dim3(SCAN_THREADS, 1, 1);
    cfg.dynamicSmemBytes = SCAN_SMEM_BYTES;
    cfg.stream = 0;
    cudaLaunchAttribute attr[1];
    attr[0].id = cudaLaunchAttributeClusterDimension;
    attr[0].val.clusterDim.x = 16;
    attr[0].val.clusterDim.y = 1;
    attr[0].val.clusterDim.z = 1;
    cfg.attrs = attr;
    cfg.numAttrs = 1;
    cudaLaunchKernelEx(&cfg, scan_kernel, Whh, bhh);

    att_logits_kernel<<<128, 128>>>(watt);
    att_softmax_kernel<<<1, 1024>>>();
    att_out_kernel<<<32, 512>>>();
    att_final_kernel<<<1, 512>>>(out);
}

// round 2
// speedup vs baseline: 1.0788x; 1.0788x over previous
#include <cuda_runtime.h>
#include <cuda_bf16.h>
#include <cstdint>
#include <cstddef>

// ---------------------------------------------------------------------------
// Problem constants
// ---------------------------------------------------------------------------
#define N_CODES 4880
#define T_STEPS 4096
#define VDIM    512
#define HD      512
#define G3      1536   // 3*HD

typedef unsigned long long ull;

// ---------------------------------------------------------------------------
// Scratch (device globals — no allocation allowed)
// ---------------------------------------------------------------------------
__device__ float g_visit[(size_t)T_STEPS * VDIM];     // 8 MB
__device__ float g_gi[(size_t)T_STEPS * G3];          // 24 MB
__device__ float g_hs[(size_t)T_STEPS * HD];          // 8 MB
__device__ float g_logits[T_STEPS];
__device__ float g_alpha[T_STEPS];
__device__ float g_part[32 * HD];

// ---------------------------------------------------------------------------
// Helpers
// ---------------------------------------------------------------------------
__device__ __forceinline__ unsigned smem_u32(const void* p) {
    unsigned a;
    asm("{ .reg .u64 t; cvta.to.shared.u64 t, %1; cvt.u32.u64 %0, t; }"
        : "=r"(a) : "l"(p));
    return a;
}

__device__ __forceinline__ ull pk2(float a, float b) {
    ull r; asm("mov.b64 %0, {%1, %2};" : "=l"(r) : "f"(a), "f"(b)); return r;
}
__device__ __forceinline__ ull pk2dup(float a) { return pk2(a, a); }
__device__ __forceinline__ void fma2(ull& d, ull a, ull b) {
    asm("fma.rn.f32x2 %0, %1, %2, %0;" : "+l"(d) : "l"(a), "l"(b));
}
__device__ __forceinline__ float2 upk2(ull v) {
    float2 r; asm("mov.b64 {%0, %1}, %2;" : "=f"(r.x), "=f"(r.y) : "l"(v));
    return r;
}

__device__ __forceinline__ void cluster_sync_all() {
    asm volatile("barrier.cluster.arrive.aligned;" ::: "memory");
    asm volatile("barrier.cluster.wait.aligned;" ::: "memory");
}

// ---------------------------------------------------------------------------
// GEMM1: visit[t][d] = sum_k H[k][t] * X[k][d]
//   t: 4096 (BM=128), d: 512 (BN=64), k: 4880 (BK=16)
//   256 threads, 8x4 register tile, f32x2-packed along m
// ---------------------------------------------------------------------------
__global__ void __launch_bounds__(256)
gemm1_kernel(const float* __restrict__ H, const float* __restrict__ X)
{
    __shared__ float As[16 * 128];  // [kk][tt]
    __shared__ float Bs[16 * 64];   // [kk][dd]
    const int tid = threadIdx.x;
    const int t0 = blockIdx.x * 128;
    const int d0 = blockIdx.y * 64;
    const int tx = tid & 15;        // -> d
    const int ty = tid >> 4;        // -> t

    ull acc2[4][4];                 // [m-pair][n], each holds (m0,m1)
#pragma unroll
    for (int mp = 0; mp < 4; mp++)
#pragma unroll
        for (int n = 0; n < 4; n++) acc2[mp][n] = 0ull;

    for (int k0 = 0; k0 < N_CODES; k0 += 16) {
#pragma unroll
        for (int j = 0; j < 2; j++) {
            int idx = tid + (j << 8);
            int kk  = idx >> 5;
            int tt4 = (idx & 31) << 2;
            float4 v = *(const float4*)(H + (size_t)(k0 + kk) * T_STEPS + t0 + tt4);
            *(float4*)(As + (kk << 7) + tt4) = v;
        }
        {
            int kk  = tid >> 4;
            int dd4 = (tid & 15) << 2;
            float4 v = *(const float4*)(X + (size_t)(k0 + kk) * VDIM + d0 + dd4);
            *(float4*)(Bs + (kk << 6) + dd4) = v;
        }
        __syncthreads();
#pragma unroll
        for (int kk = 0; kk < 16; kk++) {
            const longlong2* ap = (const longlong2*)(As + (kk << 7) + (ty << 3));
            longlong2 a01 = ap[0];      // pairs (a0,a1),(a2,a3)
            longlong2 a23 = ap[1];      // pairs (a4,a5),(a6,a7)
            ull am[4] = {(ull)a01.x, (ull)a01.y, (ull)a23.x, (ull)a23.y};
            float4 b = *(const float4*)(Bs + (kk << 6) + (tx << 2));
            ull bd[4] = {pk2dup(b.x), pk2dup(b.y), pk2dup(b.z), pk2dup(b.w)};
#pragma unroll
            for (int mp = 0; mp < 4; mp++)
#pragma unroll
                for (int n = 0; n < 4; n++)
                    fma2(acc2[mp][n], am[mp], bd[n]);
        }
        __syncthreads();
    }
#pragma unroll
    for (int mp = 0; mp < 4; mp++) {
        float2 c0 = upk2(acc2[mp][0]);
        float2 c1 = upk2(acc2[mp][1]);
        float2 c2 = upk2(acc2[mp][2]);
        float2 c3 = upk2(acc2[mp][3]);
        size_t r0 = (size_t)(t0 + (ty << 3) + 2 * mp) * VDIM + d0 + (tx << 2);
        *(float4*)(g_visit + r0)        = make_float4(c0.x, c1.x, c2.x, c3.x);
        *(float4*)(g_visit + r0 + VDIM) = make_float4(c0.y, c1.y, c2.y, c3.y);
    }
}

// ---------------------------------------------------------------------------
// GEMM2: gi[t][g] = b_ih[g] + sum_d visit[t][d] * W_ih[g][d]
// ---------------------------------------------------------------------------
__global__ void __launch_bounds__(256)
gemm2_kernel(const float* __restrict__ Wih, const float* __restrict__ bih)
{
    __shared__ float As[16 * 128];  // [kk][tt]
    __shared__ float Bs[16 * 64];   // [kk][gg]
    const int tid = threadIdx.x;
    const int t0 = blockIdx.x * 128;
    const int g0 = blockIdx.y * 64;
    const int tx = tid & 15;
    const int ty = tid >> 4;

    ull acc2[4][4];
#pragma unroll
    for (int mp = 0; mp < 4; mp++)
#pragma unroll
        for (int n = 0; n < 4; n++) acc2[mp][n] = 0ull;

    for (int k0 = 0; k0 < VDIM; k0 += 16) {
#pragma unroll
        for (int j = 0; j < 2; j++) {
            int idx = tid + (j << 8);
            int tt  = idx >> 2;
            int kk  = (idx & 3) << 2;
            float4 v = *(const float4*)(g_visit + (size_t)(t0 + tt) * VDIM + k0 + kk);
            As[(kk + 0) * 128 + tt] = v.x;
            As[(kk + 1) * 128 + tt] = v.y;
            As[(kk + 2) * 128 + tt] = v.z;
            As[(kk + 3) * 128 + tt] = v.w;
        }
        {
            int gg = tid >> 2;
            int kk = (tid & 3) << 2;
            float4 v = *(const float4*)(Wih + (size_t)(g0 + gg) * VDIM + k0 + kk);
            Bs[(kk + 0) * 64 + gg] = v.x;
            Bs[(kk + 1) * 64 + gg] = v.y;
            Bs[(kk + 2) * 64 + gg] = v.z;
            Bs[(kk + 3) * 64 + gg] = v.w;
        }
        __syncthreads();
#pragma unroll
        for (int kk = 0; kk < 16; kk++) {
            const longlong2* ap = (const longlong2*)(As + (kk << 7) + (ty << 3));
            longlong2 a01 = ap[0];
            longlong2 a23 = ap[1];
            ull am[4] = {(ull)a01.x, (ull)a01.y, (ull)a23.x, (ull)a23.y};
            float4 b = *(const float4*)(Bs + (kk << 6) + (tx << 2));
            ull bd[4] = {pk2dup(b.x), pk2dup(b.y), pk2dup(b.z), pk2dup(b.w)};
#pragma unroll
            for (int mp = 0; mp < 4; mp++)
#pragma unroll
                for (int n = 0; n < 4; n++)
                    fma2(acc2[mp][n], am[mp], bd[n]);
        }
        __syncthreads();
    }
    float4 bv = *(const float4*)(bih + g0 + (tx << 2));
#pragma unroll
    for (int mp = 0; mp < 4; mp++) {
        float2 c0 = upk2(acc2[mp][0]);
        float2 c1 = upk2(acc2[mp][1]);
        float2 c2 = upk2(acc2[mp][2]);
        float2 c3 = upk2(acc2[mp][3]);
        size_t r0 = (size_t)(t0 + (ty << 3) + 2 * mp) * G3 + g0 + (tx << 2);
        *(float4*)(g_gi + r0)      = make_float4(c0.x + bv.x, c1.x + bv.y, c2.x + bv.z, c3.x + bv.w);
        *(float4*)(g_gi + r0 + G3) = make_float4(c0.y + bv.x, c1.y + bv.y, c2.y + bv.z, c3.y + bv.w);
    }
}

// ---------------------------------------------------------------------------
// GRU scan: 16-CTA cluster, 256 threads/CTA (8 warps), persistent.
// CTA c owns hidden units [32c, 32c+32) across all 3 gates -> 96 W_hh rows.
// Warp w (0..7) owns local rows [12w, 12w+12): 10 rows in REGISTERS (f32x2
// pairs), 2 rows in smem. All FMAs are fma.rn.f32x2.
// After reduction -> pre[96] -> one __syncthreads -> warp 0 computes gates and
// pushes hnew straight to all 16 CTAs' h buffer via st.shared::cluster.
// One aligned cluster barrier per step.
// ---------------------------------------------------------------------------
#define SCAN_THREADS 256
#define REG_ROWS 10

__global__ void __launch_bounds__(SCAN_THREADS, 1)
scan_kernel(const float* __restrict__ Whh, const float* __restrict__ bhh)
{
    __shared__ float Wsh[16 * 512];   // 8 warps x 2 smem rows
    __shared__ float hb[2 * 512];
    __shared__ float pre[96];
    __shared__ float bsh[96];

    const int tid  = threadIdx.x;
    const int lane = tid & 31;
    const int w    = tid >> 5;          // 0..7
    const int cta  = blockIdx.x;        // cluster rank

    // --- one-time weight staging ---
    ull wreg[REG_ROWS][8];              // 10 rows x 16 floats as 8 f32x2
#pragma unroll
    for (int i = 0; i < REG_ROWS; i++) {
        int r = w * 12 + i;
        int grow = ((r >> 5) << 9) + (cta << 5) + (r & 31);
        const longlong2* src =
            (const longlong2*)(Whh + (size_t)grow * HD + (lane << 2));
#pragma unroll
        for (int k = 0; k < 4; k++) {
            longlong2 q = src[k * 32];  // stride 128 floats
            wreg[i][2 * k]     = (ull)q.x;
            wreg[i][2 * k + 1] = (ull)q.y;
        }
    }
#pragma unroll
    for (int i = REG_ROWS; i < 12; i++) {
        int r = w * 12 + i;
        int grow = ((r >> 5) << 9) + (cta << 5) + (r & 31);
        const float* src = Whh + (size_t)grow * HD + (lane << 2);
        float* dst = Wsh + ((w * 2 + (i - REG_ROWS)) << 9) + (lane << 2);
#pragma unroll
        for (int k = 0; k < 4; k++)
            *(float4*)(dst + (k << 7)) = *(const float4*)(src + (k << 7));
    }
    if (tid < 96) {
        int r = tid;
        int grow = ((r >> 5) << 9) + (cta << 5) + (r & 31);
        bsh[r] = bhh[grow];
    }
    for (int i = tid; i < HD; i += SCAN_THREADS) hb[i] = 0.0f;  // h_0 = 0

    // preload gi for t=0 (gate warp only)
    float gir = 0.f, giz = 0.f, gin = 0.f;
    if (w == 0) {
        const float* gp = g_gi + (cta << 5) + lane;
        gir = __ldg(gp);
        giz = __ldg(gp + HD);
        gin = __ldg(gp + 2 * HD);
    }
    __syncthreads();
    cluster_sync_all();

    for (int t = 0; t < T_STEPS; t++) {
        const int cur = t & 1, nxt = cur ^ 1;
        const float* hcur = hb + (cur << 9);

        // prefetch gi for step t+1 (latency hidden behind matvec)
        float girn = 0.f, gizn = 0.f, ginn = 0.f;
        if (w == 0) {
            int tn = (t + 1 < T_STEPS) ? t + 1 : t;
            const float* gp = g_gi + (size_t)tn * G3 + (cta << 5) + lane;
            girn = __ldg(gp);
            gizn = __ldg(gp + HD);
            ginn = __ldg(gp + 2 * HD);
        }

        // h slice: 16 floats per lane as 8 f32x2
        ull h2[8];
        {
            const longlong2* hp = (const longlong2*)(hcur + (lane << 2));
#pragma unroll
            for (int k = 0; k < 4; k++) {
                longlong2 q = hp[k * 32];
                h2[2 * k]     = (ull)q.x;
                h2[2 * k + 1] = (ull)q.y;
            }
        }

        float accs[12];
#pragma unroll
        for (int i = 0; i < REG_ROWS; i++) {
            ull a = 0ull;
#pragma unroll
            for (int k = 0; k < 8; k++) fma2(a, wreg[i][k], h2[k]);
            float2 u = upk2(a);
            accs[i] = u.x + u.y;
        }
#pragma unroll
        for (int i = REG_ROWS; i < 12; i++) {
            const longlong2* wp = (const longlong2*)
                (Wsh + ((w * 2 + (i - REG_ROWS)) << 9) + (lane << 2));
            ull a = 0ull;
#pragma unroll
            for (int k = 0; k < 4; k++) {
                longlong2 q = wp[k * 32];
                fma2(a, (ull)q.x, h2[2 * k]);
                fma2(a, (ull)q.y, h2[2 * k + 1]);
            }
            float2 u = upk2(a);
            accs[i] = u.x + u.y;
        }
#pragma unroll
        for (int i = 0; i < 12; i++) {
            float s = accs[i];
            s += __shfl_xor_sync(0xffffffffu, s, 16);
            s += __shfl_xor_sync(0xffffffffu, s, 8);
            s += __shfl_xor_sync(0xffffffffu, s, 4);
            s += __shfl_xor_sync(0xffffffffu, s, 2);
            s += __shfl_xor_sync(0xffffffffu, s, 1);
            if (lane == i) pre[w * 12 + i] = s + bsh[w * 12 + i];
        }
        __syncthreads();

        // gate math + 16-way DSMEM broadcast (warp 0)
        if (w == 0) {
            int u = lane;
            float hold = hcur[(cta << 5) + u];
            float hr = pre[u];
            float hz = pre[32 + u];
            float hn = pre[64 + u];
            float rg = 1.0f / (1.0f + __expf(-(gir + hr)));
            float zg = 1.0f / (1.0f + __expf(-(giz + hz)));
            float ng = tanhf(gin + rg * hn);
            float hnew = (1.0f - zg) * ng + zg * hold;
            g_hs[(size_t)t * HD + (cta << 5) + u] = hnew;
            unsigned laddr = smem_u32(&hb[(nxt << 9) + (cta << 5) + u]);
#pragma unroll
            for (int rk = 0; rk < 16; rk++) {
                asm volatile(
                    "{ .reg .u32 ra; mapa.shared::cluster.u32 ra, %0, %1; "
                    "st.shared::cluster.f32 [ra], %2; }"
                    :: "r"(laddr), "r"(rk), "f"(hnew));
            }
        }
        gir = girn; giz = gizn; gin = ginn;

        cluster_sync_all();   // arrive releases the DSMEM stores
    }
}

// ---------------------------------------------------------------------------
// Attention pooling
// ---------------------------------------------------------------------------
__global__ void __launch_bounds__(128)
att_logits_kernel(const float* __restrict__ watt)
{
    int w = blockIdx.x * 4 + (threadIdx.x >> 5);   // 0..511
    int lane = threadIdx.x & 31;
    for (int i = 0; i < 8; i++) {
        int t = w * 8 + i;
        const float* hp = g_hs + (size_t)t * HD;
        float acc = 0.f;
#pragma unroll
        for (int k = 0; k < 16; k++)
            acc += hp[lane + (k << 5)] * watt[lane + (k << 5)];
        acc += __shfl_xor_sync(0xffffffffu, acc, 16);
        acc += __shfl_xor_sync(0xffffffffu, acc, 8);
        acc += __shfl_xor_sync(0xffffffffu, acc, 4);
        acc += __shfl_xor_sync(0xffffffffu, acc, 2);
        acc += __shfl_xor_sync(0xffffffffu, acc, 1);
        if (lane == 0) g_logits[t] = acc;
    }
}

__global__ void __launch_bounds__(1024)
att_softmax_kernel()
{
    __shared__ float red[1024];
    int tid = threadIdx.x;
    float l[4];
    float mx = -1e30f;
#pragma unroll
    for (int i = 0; i < 4; i++) {
        l[i] = g_logits[tid + (i << 10)];
        mx = fmaxf(mx, l[i]);
    }
    red[tid] = mx;
    __syncthreads();
    for (int s = 512; s > 0; s >>= 1) {
        if (tid < s) red[tid] = fmaxf(red[tid], red[tid + s]);
        __syncthreads();
    }
    mx = red[0];
    __syncthreads();
    float e[4];
    float se = 0.f;
#pragma unroll
    for (int i = 0; i < 4; i++) {
        e[i] = __expf(l[i] - mx);
        se += e[i];
    }
    red[tid] = se;
    __syncthreads();
    for (int s = 512; s > 0; s >>= 1) {
        if (tid < s) red[tid] += red[tid + s];
        __syncthreads();
    }
    float inv = 1.0f / red[0];
#pragma unroll
    for (int i = 0; i < 4; i++)
        g_alpha[tid + (i << 10)] = e[i] * inv;
}

__global__ void __launch_bounds__(512)
att_out_kernel()
{
    int b = blockIdx.x;     // 0..31
    int d = threadIdx.x;    // 0..511
    float acc = 0.f;
    for (int i = 0; i < 128; i++) {
        int t = b * 128 + i;
        acc += g_alpha[t] * g_hs[(size_t)t * HD + d];
    }
    g_part[b * HD + d] = acc;
}

__global__ void __launch_bounds__(512)
att_final_kernel(float* __restrict__ out)
{
    int d = threadIdx.x;
    float acc = 0.f;
#pragma unroll
    for (int b = 0; b < 32; b++)
        acc += g_part[b * HD + d];
    out[d] = acc;
}

// ---------------------------------------------------------------------------
// Launch
// ---------------------------------------------------------------------------
extern "C" void kernel_launch(void* const* d_in, const int* in_sizes, int n_in,
                              void* d_out, int out_size)
{
    const float* H    = (const float*)d_in[0];
    // d_in[1] = TE (unused by reference)
    const float* X    = (const float*)d_in[2];
    const float* Wih  = (const float*)d_in[3];
    const float* Whh  = (const float*)d_in[4];
    const float* bih  = (const float*)d_in[5];
    const float* bhh  = (const float*)d_in[6];
    const float* watt = (const float*)d_in[7];
    float* out = (float*)d_out;

    gemm1_kernel<<<dim3(32, 8), 256>>>(H, X);
    gemm2_kernel<<<dim3(32, 24), 256>>>(Wih, bih);

    cudaFuncSetAttribute(scan_kernel,
                         cudaFuncAttributeNonPortableClusterSizeAllowed, 1);

    cudaLaunchConfig_t cfg = {};
    cfg.gridDim = dim3(16, 1, 1);
    cfg.blockDim = dim3(SCAN_THREADS, 1, 1);
    cfg.dynamicSmemBytes = 0;
    cfg.stream = 0;
    cudaLaunchAttribute attr[1];
    attr[0].id = cudaLaunchAttributeClusterDimension;
    attr[0].val.clusterDim.x = 16;
    attr[0].val.clusterDim.y = 1;
    attr[0].val.clusterDim.z = 1;
    cfg.attrs = attr;
    cfg.numAttrs = 1;
    cudaLaunchKernelEx(&cfg, scan_kernel, Whh, bhh);

    att_logits_kernel<<<128, 128>>>(watt);
    att_softmax_kernel<<<1, 1024>>>();
    att_out_kernel<<<32, 512>>>();
    att_final_kernel<<<1, 512>>>(out);
}

// round 3
// speedup vs baseline: 1.4704x; 1.3630x over previous
#include <cuda_runtime.h>
#include <cuda_bf16.h>
#include <cstdint>
#include <cstddef>

// ---------------------------------------------------------------------------
// Problem constants
// ---------------------------------------------------------------------------
#define N_CODES 4880
#define T_STEPS 4096
#define VDIM    512
#define HD      512
#define G3      1536   // 3*HD

typedef unsigned long long ull;

// ---------------------------------------------------------------------------
// Scratch (device globals — no allocation allowed)
// ---------------------------------------------------------------------------
__device__ float g_visit[(size_t)T_STEPS * VDIM];     // 8 MB
__device__ float g_gi[(size_t)T_STEPS * G3];          // 24 MB
__device__ float g_hs[(size_t)T_STEPS * HD];          // 8 MB
__device__ float g_logits[T_STEPS];
__device__ float g_alpha[T_STEPS];
__device__ float g_part[32 * HD];

// ---------------------------------------------------------------------------
// Helpers
// ---------------------------------------------------------------------------
__device__ __forceinline__ unsigned smem_u32(const void* p) {
    unsigned a;
    asm("{ .reg .u64 t; cvta.to.shared.u64 t, %1; cvt.u32.u64 %0, t; }"
        : "=r"(a) : "l"(p));
    return a;
}
__device__ __forceinline__ ull pk2(float a, float b) {
    ull r; asm("mov.b64 %0, {%1, %2};" : "=l"(r) : "f"(a), "f"(b)); return r;
}
__device__ __forceinline__ ull pk2dup(float a) { return pk2(a, a); }
__device__ __forceinline__ void fma2(ull& d, ull a, ull b) {
    asm("fma.rn.f32x2 %0, %1, %2, %0;" : "+l"(d) : "l"(a), "l"(b));
}
__device__ __forceinline__ float2 upk2(ull v) {
    float2 r; asm("mov.b64 {%0, %1}, %2;" : "=f"(r.x), "=f"(r.y) : "l"(v));
    return r;
}
__device__ __forceinline__ float tanh_fast(float x) {
    float r; asm("tanh.approx.f32 %0, %1;" : "=f"(r) : "f"(x)); return r;
}
__device__ __forceinline__ void cluster_sync_all() {
    asm volatile("barrier.cluster.arrive.aligned;" ::: "memory");
    asm volatile("barrier.cluster.wait.aligned;" ::: "memory");
}
__device__ __forceinline__ void mbar_init(unsigned a, unsigned cnt) {
    asm volatile("mbarrier.init.shared.b64 [%0], %1;" :: "r"(a), "r"(cnt) : "memory");
}
__device__ __forceinline__ void mbar_expect(unsigned a, unsigned bytes) {
    asm volatile("mbarrier.arrive.expect_tx.shared.b64 _, [%0], %1;"
                 :: "r"(a), "r"(bytes) : "memory");
}
__device__ __forceinline__ void mbar_wait(unsigned a, unsigned parity) {
    asm volatile(
        "{\n\t.reg .pred P;\n\t"
        "LW_%=:\n\t"
        "mbarrier.try_wait.parity.acquire.cluster.shared::cta.b64 P, [%0], %1, 0x989680;\n\t"
        "@P bra.uni LD_%=;\n\t"
        "bra.uni LW_%=;\n\t"
        "LD_%=:\n\t}"
        :: "r"(a), "r"(parity) : "memory");
}
// store val into rank rk's smem at (local-pattern) addr ld, completing tx on
// rank rk's mbarrier at (local-pattern) addr lm
__device__ __forceinline__ void st_async_remote(unsigned ld, unsigned lm,
                                                int rk, unsigned val) {
    asm volatile(
        "{\n\t.reg .u32 ra, rb;\n\t"
        "mapa.shared::cluster.u32 ra, %0, %2;\n\t"
        "mapa.shared::cluster.u32 rb, %1, %2;\n\t"
        "st.async.shared::cluster.mbarrier::complete_tx::bytes.b32 [ra], %3, [rb];\n\t}"
        :: "r"(ld), "r"(lm), "r"(rk), "r"(val) : "memory");
}

// ---------------------------------------------------------------------------
// GEMM1: visit[t][d] = sum_k H[k][t] * X[k][d]
// ---------------------------------------------------------------------------
__global__ void __launch_bounds__(256)
gemm1_kernel(const float* __restrict__ H, const float* __restrict__ X)
{
    __shared__ float As[16 * 128];
    __shared__ float Bs[16 * 64];
    const int tid = threadIdx.x;
    const int t0 = blockIdx.x * 128;
    const int d0 = blockIdx.y * 64;
    const int tx = tid & 15;
    const int ty = tid >> 4;

    ull acc2[4][4];
#pragma unroll
    for (int mp = 0; mp < 4; mp++)
#pragma unroll
        for (int n = 0; n < 4; n++) acc2[mp][n] = 0ull;

    for (int k0 = 0; k0 < N_CODES; k0 += 16) {
#pragma unroll
        for (int j = 0; j < 2; j++) {
            int idx = tid + (j << 8);
            int kk  = idx >> 5;
            int tt4 = (idx & 31) << 2;
            float4 v = *(const float4*)(H + (size_t)(k0 + kk) * T_STEPS + t0 + tt4);
            *(float4*)(As + (kk << 7) + tt4) = v;
        }
        {
            int kk  = tid >> 4;
            int dd4 = (tid & 15) << 2;
            float4 v = *(const float4*)(X + (size_t)(k0 + kk) * VDIM + d0 + dd4);
            *(float4*)(Bs + (kk << 6) + dd4) = v;
        }
        __syncthreads();
#pragma unroll
        for (int kk = 0; kk < 16; kk++) {
            const longlong2* ap = (const longlong2*)(As + (kk << 7) + (ty << 3));
            longlong2 a01 = ap[0];
            longlong2 a23 = ap[1];
            ull am[4] = {(ull)a01.x, (ull)a01.y, (ull)a23.x, (ull)a23.y};
            float4 b = *(const float4*)(Bs + (kk << 6) + (tx << 2));
            ull bd[4] = {pk2dup(b.x), pk2dup(b.y), pk2dup(b.z), pk2dup(b.w)};
#pragma unroll
            for (int mp = 0; mp < 4; mp++)
#pragma unroll
                for (int n = 0; n < 4; n++)
                    fma2(acc2[mp][n], am[mp], bd[n]);
        }
        __syncthreads();
    }
#pragma unroll
    for (int mp = 0; mp < 4; mp++) {
        float2 c0 = upk2(acc2[mp][0]);
        float2 c1 = upk2(acc2[mp][1]);
        float2 c2 = upk2(acc2[mp][2]);
        float2 c3 = upk2(acc2[mp][3]);
        size_t r0 = (size_t)(t0 + (ty << 3) + 2 * mp) * VDIM + d0 + (tx << 2);
        *(float4*)(g_visit + r0)        = make_float4(c0.x, c1.x, c2.x, c3.x);
        *(float4*)(g_visit + r0 + VDIM) = make_float4(c0.y, c1.y, c2.y, c3.y);
    }
}

// ---------------------------------------------------------------------------
// GEMM2: gi[t][g] = b_ih[g] + sum_d visit[t][d] * W_ih[g][d]
// ---------------------------------------------------------------------------
__global__ void __launch_bounds__(256)
gemm2_kernel(const float* __restrict__ Wih, const float* __restrict__ bih)
{
    __shared__ float As[16 * 128];
    __shared__ float Bs[16 * 64];
    const int tid = threadIdx.x;
    const int t0 = blockIdx.x * 128;
    const int g0 = blockIdx.y * 64;
    const int tx = tid & 15;
    const int ty = tid >> 4;

    ull acc2[4][4];
#pragma unroll
    for (int mp = 0; mp < 4; mp++)
#pragma unroll
        for (int n = 0; n < 4; n++) acc2[mp][n] = 0ull;

    for (int k0 = 0; k0 < VDIM; k0 += 16) {
#pragma unroll
        for (int j = 0; j < 2; j++) {
            int idx = tid + (j << 8);
            int tt  = idx >> 2;
            int kk  = (idx & 3) << 2;
            float4 v = *(const float4*)(g_visit + (size_t)(t0 + tt) * VDIM + k0 + kk);
            As[(kk + 0) * 128 + tt] = v.x;
            As[(kk + 1) * 128 + tt] = v.y;
            As[(kk + 2) * 128 + tt] = v.z;
            As[(kk + 3) * 128 + tt] = v.w;
        }
        {
            int gg = tid >> 2;
            int kk = (tid & 3) << 2;
            float4 v = *(const float4*)(Wih + (size_t)(g0 + gg) * VDIM + k0 + kk);
            Bs[(kk + 0) * 64 + gg] = v.x;
            Bs[(kk + 1) * 64 + gg] = v.y;
            Bs[(kk + 2) * 64 + gg] = v.z;
            Bs[(kk + 3) * 64 + gg] = v.w;
        }
        __syncthreads();
#pragma unroll
        for (int kk = 0; kk < 16; kk++) {
            const longlong2* ap = (const longlong2*)(As + (kk << 7) + (ty << 3));
            longlong2 a01 = ap[0];
            longlong2 a23 = ap[1];
            ull am[4] = {(ull)a01.x, (ull)a01.y, (ull)a23.x, (ull)a23.y};
            float4 b = *(const float4*)(Bs + (kk << 6) + (tx << 2));
            ull bd[4] = {pk2dup(b.x), pk2dup(b.y), pk2dup(b.z), pk2dup(b.w)};
#pragma unroll
            for (int mp = 0; mp < 4; mp++)
#pragma unroll
                for (int n = 0; n < 4; n++)
                    fma2(acc2[mp][n], am[mp], bd[n]);
        }
        __syncthreads();
    }
    float4 bv = *(const float4*)(bih + g0 + (tx << 2));
#pragma unroll
    for (int mp = 0; mp < 4; mp++) {
        float2 c0 = upk2(acc2[mp][0]);
        float2 c1 = upk2(acc2[mp][1]);
        float2 c2 = upk2(acc2[mp][2]);
        float2 c3 = upk2(acc2[mp][3]);
        size_t r0 = (size_t)(t0 + (ty << 3) + 2 * mp) * G3 + g0 + (tx << 2);
        *(float4*)(g_gi + r0)      = make_float4(c0.x + bv.x, c1.x + bv.y, c2.x + bv.z, c3.x + bv.w);
        *(float4*)(g_gi + r0 + G3) = make_float4(c0.y + bv.x, c1.y + bv.y, c2.y + bv.z, c3.y + bv.w);
    }
}

// ---------------------------------------------------------------------------
// GRU scan: 16-CTA cluster, 256 threads (8 warps), mbarrier+st.async sync.
//
// CTA c owns hidden units [32c, 32c+32) across 3 gates -> 96 W_hh rows.
// Warp w: 12 rows as 6 groups of 2; lane = (c4 = lane&15 -> 32-float h chunk,
// rh = lane>>4 -> row in group). Groups 0..4 weights in registers (f32x2),
// group 5 in smem. h stored TRANSPOSED: hT[buf][j(0..7)][c(0..15)] as float4
// so strided chunk loads are conflict-free.
// Gates: warps 0..3 (lane: unit u = w*8+(lane&7), rank group m = lane>>3),
// sigmoid/tanh via MUFU tanh.approx, fan-out via st.async -> remote mbarrier.
// ---------------------------------------------------------------------------
#define SCAN_THREADS 256

__global__ void __launch_bounds__(SCAN_THREADS, 1)
scan_kernel(const float* __restrict__ Whh, const float* __restrict__ bhh)
{
    __shared__ float4 Wsh4[8][2][8][16];  // [warp][rh][j][c] : 32 KB
    __shared__ float  hT[2 * HD];         // transposed h, 2 buffers
    __shared__ float  pre[96];
    __shared__ float  bsh[96];
    __shared__ ull    mbar[2];

    const int tid  = threadIdx.x;
    const int lane = tid & 31;
    const int w    = tid >> 5;
    const int cta  = blockIdx.x;          // cluster rank
    const int c4   = lane & 15;           // h-chunk index
    const int rh   = lane >> 4;           // row within group

    // --- one-time weight staging ---
    ull wreg[5][16];                      // groups 0..4 in registers
#pragma unroll
    for (int g = 0; g < 5; g++) {
        int r = w * 12 + g * 2 + rh;
        int grow = ((r >> 5) << 9) + (cta << 5) + (r & 31);
        const ull* src = (const ull*)(Whh + (size_t)grow * HD + (c4 << 5));
#pragma unroll
        for (int k = 0; k < 16; k++) wreg[g][k] = src[k];
    }
    {   // group 5 -> smem, layout [w][rh][j][c]
        int r = w * 12 + 10 + rh;
        int grow = ((r >> 5) << 9) + (cta << 5) + (r & 31);
        const float4* src = (const float4*)(Whh + (size_t)grow * HD + (c4 << 5));
#pragma unroll
        for (int j = 0; j < 8; j++) Wsh4[w][rh][j][c4] = src[j];
    }
    if (tid < 96) {
        int grow = ((tid >> 5) << 9) + (cta << 5) + (tid & 31);
        bsh[tid] = bhh[grow];
    }
    for (int i = tid; i < HD; i += SCAN_THREADS) hT[i] = 0.0f;  // h_0 = 0 (buf 0)
    if (tid == 0) { mbar_init(smem_u32(&mbar[0]), 1); mbar_init(smem_u32(&mbar[1]), 1); }
    __syncthreads();
    cluster_sync_all();   // all peers' mbarriers/buffers initialized

    // gi preload for t=0 (gate warps 0..3)
    const int u_loc = ((w & 3) << 3) + (lane & 7);
    const int m_rk  = lane >> 3;                 // rank group (gate warps)
    float gir = 0.f, giz = 0.f, gin = 0.f;
    if (w < 4) {
        const float* gp = g_gi + (cta << 5) + u_loc;
        gir = __ldg(gp); giz = __ldg(gp + HD); gin = __ldg(gp + 2 * HD);
    }

    int ph0 = 0, ph1 = 0;
    for (int t = 0; t < T_STEPS; t++) {
        const int cb = t & 1;          // current h buffer
        const int nb = cb ^ 1;         // buffer/barrier filled this step

        if (tid == 0) mbar_expect(smem_u32(&mbar[nb]), 2048u);

        // prefetch gi for t+1
        float girn = 0.f, gizn = 0.f, ginn = 0.f;
        if (w < 4) {
            int tn = (t + 1 < T_STEPS) ? t + 1 : t;
            const float* gp = g_gi + (size_t)tn * G3 + (cta << 5) + u_loc;
            girn = __ldg(gp); gizn = __ldg(gp + HD); ginn = __ldg(gp + 2 * HD);
        }

        // load h chunk (32 floats) — transposed layout, conflict-free
        ull h2[16];
        {
            const longlong2* hp = (const longlong2*)(hT + (cb << 9));
#pragma unroll
            for (int j = 0; j < 8; j++) {
                longlong2 q = hp[(j << 4) + c4];
                h2[2 * j]     = (ull)q.x;
                h2[2 * j + 1] = (ull)q.y;
            }
        }

        // matvec: 6 groups
        ull a2[6];
#pragma unroll
        for (int g = 0; g < 5; g++) {
            ull a = 0ull;
#pragma unroll
            for (int k = 0; k < 16; k++) fma2(a, wreg[g][k], h2[k]);
            a2[g] = a;
        }
        {
            ull a = 0ull;
            const longlong2* wp = (const longlong2*)&Wsh4[w][rh][0][c4];
#pragma unroll
            for (int j = 0; j < 8; j++) {
                longlong2 q = wp[j << 4];     // stride 16 float4s
                fma2(a, (ull)q.x, h2[2 * j]);
                fma2(a, (ull)q.y, h2[2 * j + 1]);
            }
            a2[5] = a;
        }

        // reduce across 16 lanes (4 shfl levels), 6 groups interleaved
        float accs[6];
#pragma unroll
        for (int g = 0; g < 6; g++) { float2 u = upk2(a2[g]); accs[g] = u.x + u.y; }
#pragma unroll
        for (int d = 8; d > 0; d >>= 1)
#pragma unroll
            for (int g = 0; g < 6; g++)
                accs[g] += __shfl_xor_sync(0xffffffffu, accs[g], d);
        if (c4 == 0) {
#pragma unroll
            for (int g = 0; g < 6; g++) {
                int r = w * 12 + g * 2 + rh;
                pre[r] = accs[g] + bsh[r];
            }
        }
        __syncthreads();

        // gates + fan-out (warps 0..3; lane -> unit u_loc, ranks m_rk*4..+3)
        if (w < 4) {
            int u = u_loc;
            int hoff = (cb << 9) + ((u >> 2) << 6) + (cta << 2) + (u & 3);
            float hold = hT[hoff];
            float pr = pre[u], pz = pre[32 + u], pn = pre[64 + u];
            float rg = fmaf(0.5f, tanh_fast(0.5f * (gir + pr)), 0.5f);
            float zg = fmaf(0.5f, tanh_fast(0.5f * (giz + pz)), 0.5f);
            float ng = tanh_fast(fmaf(rg, pn, gin));
            float hnew = fmaf(zg, hold - ng, ng);
            if (m_rk == 0) g_hs[(size_t)t * HD + (cta << 5) + u] = hnew;
            unsigned ld = smem_u32(&hT[(nb << 9) + ((u >> 2) << 6) + (cta << 2) + (u & 3)]);
            unsigned lm = smem_u32(&mbar[nb]);
            unsigned hv = __float_as_uint(hnew);
#pragma unroll
            for (int q = 0; q < 4; q++)
                st_async_remote(ld, lm, (m_rk << 2) + q, hv);
        }
        gir = girn; giz = gizn; gin = ginn;

        // wait for all 2048 bytes of h_{t+1}
        unsigned par = nb ? (unsigned)ph1 : (unsigned)ph0;
        mbar_wait(smem_u32(&mbar[nb]), par);
        if (nb) ph1 ^= 1; else ph0 ^= 1;
    }
    cluster_sync_all();   // don't exit while peers may still touch our smem
}

// ---------------------------------------------------------------------------
// Attention pooling
// ---------------------------------------------------------------------------
__global__ void __launch_bounds__(128)
att_logits_kernel(const float* __restrict__ watt)
{
    int w = blockIdx.x * 4 + (threadIdx.x >> 5);
    int lane = threadIdx.x & 31;
    for (int i = 0; i < 8; i++) {
        int t = w * 8 + i;
        const float* hp = g_hs + (size_t)t * HD;
        float acc = 0.f;
#pragma unroll
        for (int k = 0; k < 16; k++)
            acc += hp[lane + (k << 5)] * watt[lane + (k << 5)];
        acc += __shfl_xor_sync(0xffffffffu, acc, 16);
        acc += __shfl_xor_sync(0xffffffffu, acc, 8);
        acc += __shfl_xor_sync(0xffffffffu, acc, 4);
        acc += __shfl_xor_sync(0xffffffffu, acc, 2);
        acc += __shfl_xor_sync(0xffffffffu, acc, 1);
        if (lane == 0) g_logits[t] = acc;
    }
}

__global__ void __launch_bounds__(1024)
att_softmax_kernel()
{
    __shared__ float red[1024];
    int tid = threadIdx.x;
    float l[4];
    float mx = -1e30f;
#pragma unroll
    for (int i = 0; i < 4; i++) {
        l[i] = g_logits[tid + (i << 10)];
        mx = fmaxf(mx, l[i]);
    }
    red[tid] = mx;
    __syncthreads();
    for (int s = 512; s > 0; s >>= 1) {
        if (tid < s) red[tid] = fmaxf(red[tid], red[tid + s]);
        __syncthreads();
    }
    mx = red[0];
    __syncthreads();
    float e[4];
    float se = 0.f;
#pragma unroll
    for (int i = 0; i < 4; i++) {
        e[i] = __expf(l[i] - mx);
        se += e[i];
    }
    red[tid] = se;
    __syncthreads();
    for (int s = 512; s > 0; s >>= 1) {
        if (tid < s) red[tid] += red[tid + s];
        __syncthreads();
    }
    float inv = 1.0f / red[0];
#pragma unroll
    for (int i = 0; i < 4; i++)
        g_alpha[tid + (i << 10)] = e[i] * inv;
}

__global__ void __launch_bounds__(512)
att_out_kernel()
{
    int b = blockIdx.x;
    int d = threadIdx.x;
    float acc = 0.f;
    for (int i = 0; i < 128; i++) {
        int t = b * 128 + i;
        acc += g_alpha[t] * g_hs[(size_t)t * HD + d];
    }
    g_part[b * HD + d] = acc;
}

__global__ void __launch_bounds__(512)
att_final_kernel(float* __restrict__ out)
{
    int d = threadIdx.x;
    float acc = 0.f;
#pragma unroll
    for (int b = 0; b < 32; b++)
        acc += g_part[b * HD + d];
    out[d] = acc;
}

// ---------------------------------------------------------------------------
// Launch
// ---------------------------------------------------------------------------
extern "C" void kernel_launch(void* const* d_in, const int* in_sizes, int n_in,
                              void* d_out, int out_size)
{
    const float* H    = (const float*)d_in[0];
    // d_in[1] = TE (unused by reference)
    const float* X    = (const float*)d_in[2];
    const float* Wih  = (const float*)d_in[3];
    const float* Whh  = (const float*)d_in[4];
    const float* bih  = (const float*)d_in[5];
    const float* bhh  = (const float*)d_in[6];
    const float* watt = (const float*)d_in[7];
    float* out = (float*)d_out;

    gemm1_kernel<<<dim3(32, 8), 256>>>(H, X);
    gemm2_kernel<<<dim3(32, 24), 256>>>(Wih, bih);

    cudaFuncSetAttribute(scan_kernel,
                         cudaFuncAttributeNonPortableClusterSizeAllowed, 1);

    cudaLaunchConfig_t cfg = {};
    cfg.gridDim = dim3(16, 1, 1);
    cfg.blockDim = dim3(SCAN_THREADS, 1, 1);
    cfg.dynamicSmemBytes = 0;
    cfg.stream = 0;
    cudaLaunchAttribute attr[1];
    attr[0].id = cudaLaunchAttributeClusterDimension;
    attr[0].val.clusterDim.x = 16;
    attr[0].val.clusterDim.y = 1;
    attr[0].val.clusterDim.z = 1;
    cfg.attrs = attr;
    cfg.numAttrs = 1;
    cudaLaunchKernelEx(&cfg, scan_kernel, Whh, bhh);

    att_logits_kernel<<<128, 128>>>(watt);
    att_softmax_kernel<<<1, 1024>>>();
    att_out_kernel<<<32, 512>>>();
    att_final_kernel<<<1, 512>>>(out);
}

// round 4
// speedup vs baseline: 1.9365x; 1.3170x over previous
#include <cuda_runtime.h>
#include <cuda_bf16.h>
#include <cstdint>
#include <cstddef>

// ---------------------------------------------------------------------------
// Problem constants
// ---------------------------------------------------------------------------
#define N_CODES 4880
#define T_STEPS 4096
#define VDIM    512
#define HD      512
#define G3      1536   // 3*HD

typedef unsigned long long ull;

// ---------------------------------------------------------------------------
// Scratch (device globals — no allocation allowed)
// ---------------------------------------------------------------------------
__device__ float g_visit[(size_t)T_STEPS * VDIM];     // 8 MB
__device__ float g_gi[(size_t)T_STEPS * G3];          // 24 MB
__device__ float g_hs[(size_t)T_STEPS * HD];          // 8 MB
__device__ float g_logits[T_STEPS];
__device__ float g_alpha[T_STEPS];
__device__ float g_part[32 * HD];

// ---------------------------------------------------------------------------
// Helpers
// ---------------------------------------------------------------------------
__device__ __forceinline__ unsigned smem_u32(const void* p) {
    unsigned a;
    asm("{ .reg .u64 t; cvta.to.shared.u64 t, %1; cvt.u32.u64 %0, t; }"
        : "=r"(a) : "l"(p));
    return a;
}
__device__ __forceinline__ unsigned mapa_u32(unsigned laddr, int rk) {
    unsigned r;
    asm("mapa.shared::cluster.u32 %0, %1, %2;" : "=r"(r) : "r"(laddr), "r"(rk));
    return r;
}
__device__ __forceinline__ ull pk2(float a, float b) {
    ull r; asm("mov.b64 %0, {%1, %2};" : "=l"(r) : "f"(a), "f"(b)); return r;
}
__device__ __forceinline__ ull pk2dup(float a) { return pk2(a, a); }
__device__ __forceinline__ void fma2(ull& d, ull a, ull b) {
    asm("fma.rn.f32x2 %0, %1, %2, %0;" : "+l"(d) : "l"(a), "l"(b));
}
__device__ __forceinline__ float2 upk2(ull v) {
    float2 r; asm("mov.b64 {%0, %1}, %2;" : "=f"(r.x), "=f"(r.y) : "l"(v));
    return r;
}
__device__ __forceinline__ float tanh_fast(float x) {
    float r; asm("tanh.approx.f32 %0, %1;" : "=f"(r) : "f"(x)); return r;
}
__device__ __forceinline__ void cluster_sync_all() {
    asm volatile("barrier.cluster.arrive.aligned;" ::: "memory");
    asm volatile("barrier.cluster.wait.aligned;" ::: "memory");
}
__device__ __forceinline__ void mbar_init(unsigned a, unsigned cnt) {
    asm volatile("mbarrier.init.shared.b64 [%0], %1;" :: "r"(a), "r"(cnt) : "memory");
}
__device__ __forceinline__ void mbar_expect(unsigned a, unsigned bytes) {
    asm volatile("mbarrier.arrive.expect_tx.shared.b64 _, [%0], %1;"
                 :: "r"(a), "r"(bytes) : "memory");
}
__device__ __forceinline__ void mbar_wait(unsigned a, unsigned parity) {
    asm volatile(
        "{\n\t.reg .pred P;\n\t"
        "LW_%=:\n\t"
        "mbarrier.try_wait.parity.acquire.cluster.shared::cta.b64 P, [%0], %1, 0x989680;\n\t"
        "@P bra.uni LD_%=;\n\t"
        "bra.uni LW_%=;\n\t"
        "LD_%=:\n\t}"
        :: "r"(a), "r"(parity) : "memory");
}
// st.async with precomputed remote (cluster-mapped) addresses
__device__ __forceinline__ void st_async_pre(unsigned ra, unsigned rb, unsigned val) {
    asm volatile(
        "st.async.shared::cluster.mbarrier::complete_tx::bytes.b32 [%0], %1, [%2];"
        :: "r"(ra), "r"(val), "r"(rb) : "memory");
}

// ---------------------------------------------------------------------------
// GEMM1: visit[t][d] = sum_k H[k][t] * X[k][d]
// ---------------------------------------------------------------------------
__global__ void __launch_bounds__(256)
gemm1_kernel(const float* __restrict__ H, const float* __restrict__ X)
{
    __shared__ float As[16 * 128];
    __shared__ float Bs[16 * 64];
    const int tid = threadIdx.x;
    const int t0 = blockIdx.x * 128;
    const int d0 = blockIdx.y * 64;
    const int tx = tid & 15;
    const int ty = tid >> 4;

    ull acc2[4][4];
#pragma unroll
    for (int mp = 0; mp < 4; mp++)
#pragma unroll
        for (int n = 0; n < 4; n++) acc2[mp][n] = 0ull;

    for (int k0 = 0; k0 < N_CODES; k0 += 16) {
#pragma unroll
        for (int j = 0; j < 2; j++) {
            int idx = tid + (j << 8);
            int kk  = idx >> 5;
            int tt4 = (idx & 31) << 2;
            float4 v = *(const float4*)(H + (size_t)(k0 + kk) * T_STEPS + t0 + tt4);
            *(float4*)(As + (kk << 7) + tt4) = v;
        }
        {
            int kk  = tid >> 4;
            int dd4 = (tid & 15) << 2;
            float4 v = *(const float4*)(X + (size_t)(k0 + kk) * VDIM + d0 + dd4);
            *(float4*)(Bs + (kk << 6) + dd4) = v;
        }
        __syncthreads();
#pragma unroll
        for (int kk = 0; kk < 16; kk++) {
            const longlong2* ap = (const longlong2*)(As + (kk << 7) + (ty << 3));
            longlong2 a01 = ap[0];
            longlong2 a23 = ap[1];
            ull am[4] = {(ull)a01.x, (ull)a01.y, (ull)a23.x, (ull)a23.y};
            float4 b = *(const float4*)(Bs + (kk << 6) + (tx << 2));
            ull bd[4] = {pk2dup(b.x), pk2dup(b.y), pk2dup(b.z), pk2dup(b.w)};
#pragma unroll
            for (int mp = 0; mp < 4; mp++)
#pragma unroll
                for (int n = 0; n < 4; n++)
                    fma2(acc2[mp][n], am[mp], bd[n]);
        }
        __syncthreads();
    }
#pragma unroll
    for (int mp = 0; mp < 4; mp++) {
        float2 c0 = upk2(acc2[mp][0]);
        float2 c1 = upk2(acc2[mp][1]);
        float2 c2 = upk2(acc2[mp][2]);
        float2 c3 = upk2(acc2[mp][3]);
        size_t r0 = (size_t)(t0 + (ty << 3) + 2 * mp) * VDIM + d0 + (tx << 2);
        *(float4*)(g_visit + r0)        = make_float4(c0.x, c1.x, c2.x, c3.x);
        *(float4*)(g_visit + r0 + VDIM) = make_float4(c0.y, c1.y, c2.y, c3.y);
    }
}

// ---------------------------------------------------------------------------
// GEMM2: gi[t][g] = b_ih[g] + sum_d visit[t][d] * W_ih[g][d]
// ---------------------------------------------------------------------------
__global__ void __launch_bounds__(256)
gemm2_kernel(const float* __restrict__ Wih, const float* __restrict__ bih)
{
    __shared__ float As[16 * 128];
    __shared__ float Bs[16 * 64];
    const int tid = threadIdx.x;
    const int t0 = blockIdx.x * 128;
    const int g0 = blockIdx.y * 64;
    const int tx = tid & 15;
    const int ty = tid >> 4;

    ull acc2[4][4];
#pragma unroll
    for (int mp = 0; mp < 4; mp++)
#pragma unroll
        for (int n = 0; n < 4; n++) acc2[mp][n] = 0ull;

    for (int k0 = 0; k0 < VDIM; k0 += 16) {
#pragma unroll
        for (int j = 0; j < 2; j++) {
            int idx = tid + (j << 8);
            int tt  = idx >> 2;
            int kk  = (idx & 3) << 2;
            float4 v = *(const float4*)(g_visit + (size_t)(t0 + tt) * VDIM + k0 + kk);
            As[(kk + 0) * 128 + tt] = v.x;
            As[(kk + 1) * 128 + tt] = v.y;
            As[(kk + 2) * 128 + tt] = v.z;
            As[(kk + 3) * 128 + tt] = v.w;
        }
        {
            int gg = tid >> 2;
            int kk = (tid & 3) << 2;
            float4 v = *(const float4*)(Wih + (size_t)(g0 + gg) * VDIM + k0 + kk);
            Bs[(kk + 0) * 64 + gg] = v.x;
            Bs[(kk + 1) * 64 + gg] = v.y;
            Bs[(kk + 2) * 64 + gg] = v.z;
            Bs[(kk + 3) * 64 + gg] = v.w;
        }
        __syncthreads();
#pragma unroll
        for (int kk = 0; kk < 16; kk++) {
            const longlong2* ap = (const longlong2*)(As + (kk << 7) + (ty << 3));
            longlong2 a01 = ap[0];
            longlong2 a23 = ap[1];
            ull am[4] = {(ull)a01.x, (ull)a01.y, (ull)a23.x, (ull)a23.y};
            float4 b = *(const float4*)(Bs + (kk << 6) + (tx << 2));
            ull bd[4] = {pk2dup(b.x), pk2dup(b.y), pk2dup(b.z), pk2dup(b.w)};
#pragma unroll
            for (int mp = 0; mp < 4; mp++)
#pragma unroll
                for (int n = 0; n < 4; n++)
                    fma2(acc2[mp][n], am[mp], bd[n]);
        }
        __syncthreads();
    }
    float4 bv = *(const float4*)(bih + g0 + (tx << 2));
#pragma unroll
    for (int mp = 0; mp < 4; mp++) {
        float2 c0 = upk2(acc2[mp][0]);
        float2 c1 = upk2(acc2[mp][1]);
        float2 c2 = upk2(acc2[mp][2]);
        float2 c3 = upk2(acc2[mp][3]);
        size_t r0 = (size_t)(t0 + (ty << 3) + 2 * mp) * G3 + g0 + (tx << 2);
        *(float4*)(g_gi + r0)      = make_float4(c0.x + bv.x, c1.x + bv.y, c2.x + bv.z, c3.x + bv.w);
        *(float4*)(g_gi + r0 + G3) = make_float4(c0.y + bv.x, c1.y + bv.y, c2.y + bv.z, c3.y + bv.w);
    }
}

// ---------------------------------------------------------------------------
// GRU scan: 16-CTA cluster, 256 threads (8 warps), BAR-FREE loop.
//
// CTA c owns hidden units [32c, 32c+32). Warp w owns units {4w..4w+3} with all
// 3 gates -> 12 rows. Row (gate g3, unit-low ui): group g = g3*2 + (ui>>1),
// rh = ui&1 (lane>>4). Groups 0..4 weights in registers (f32x2), group 5 in
// smem. Lane c4 = lane&15 handles h chunk [32*c4, 32*c4+32) (= CTA c4's units,
// transposed hT layout, conflict-free).
// After the xor-butterfly (8,4,2,1) every lane holds all 6 reduced group sums
// for its rh half -> each lane gate-computes one unit (ui = ((lane&1)<<1)|rh)
// and fans out to 2 ranks (q = (lane>>1)&7 -> ranks 2q, 2q+1) via st.async
// with mapa-precomputed addresses. No bar.sync in the loop.
// ---------------------------------------------------------------------------
#define SCAN_THREADS 256

__global__ void __launch_bounds__(SCAN_THREADS, 1)
scan_kernel(const float* __restrict__ Whh, const float* __restrict__ bhh)
{
    __shared__ float4 Wsh4[8][2][8][16];  // group-5 weights [w][rh][j][c4] : 32 KB
    __shared__ float  hT[2 * HD];         // transposed h, 2 buffers
    __shared__ ull    mbar[2];

    const int tid  = threadIdx.x;
    const int lane = tid & 31;
    const int w    = tid >> 5;
    const int cta  = blockIdx.x;          // cluster rank
    const int c4   = lane & 15;           // h-chunk (source CTA) index
    const int rh   = lane >> 4;

    // gate-lane identity
    const int ui    = ((lane & 1) << 1) | rh;   // unit-low index 0..3
    const int q     = (lane >> 1) & 7;          // rank-pair 0..7
    const int ul    = (w << 2) + ui;            // local unit 0..31
    const int u_gbl = (cta << 5) + ul;          // global unit

    // --- one-time weight staging ---
    // row(g, rh) = (g>>1)*512 + cta*32 + 4w + ((g&1)<<1) + rh
    ull wreg[5][16];
#pragma unroll
    for (int g = 0; g < 5; g++) {
        int grow = ((g >> 1) << 9) + (cta << 5) + (w << 2) + ((g & 1) << 1) + rh;
        const ull* src = (const ull*)(Whh + (size_t)grow * HD + (c4 << 5));
#pragma unroll
        for (int k = 0; k < 16; k++) wreg[g][k] = src[k];
    }
    {   // group 5 (gate n, ui = 2+rh) -> smem
        int grow = (2 << 9) + (cta << 5) + (w << 2) + 2 + rh;
        const float4* src = (const float4*)(Whh + (size_t)grow * HD + (c4 << 5));
#pragma unroll
        for (int j = 0; j < 8; j++) Wsh4[w][rh][j][c4] = src[j];
    }
    // per-lane gate biases (r, z, n rows of this lane's unit)
    const float br = bhh[u_gbl];
    const float bz = bhh[HD + u_gbl];
    const float bn = bhh[2 * HD + u_gbl];

    for (int i = tid; i < HD; i += SCAN_THREADS) hT[i] = 0.0f;  // h_0 = 0 (buf 0)
    if (tid == 0) { mbar_init(smem_u32(&mbar[0]), 1); mbar_init(smem_u32(&mbar[1]), 1); }
    __syncthreads();
    cluster_sync_all();   // all peers' mbarriers/buffers initialized

    // precompute remote addresses for the 2 target ranks x 2 buffers
    const int hoffb = ((ul >> 2) << 6) + (cta << 2) + (ul & 3);
    unsigned rdata[2][2], rbar[2][2];
#pragma unroll
    for (int b = 0; b < 2; b++) {
        unsigned ld = smem_u32(&hT[(b << 9) + hoffb]);
        unsigned lm = smem_u32(&mbar[b]);
#pragma unroll
        for (int r = 0; r < 2; r++) {
            rdata[b][r] = mapa_u32(ld, (q << 1) + r);
            rbar[b][r]  = mapa_u32(lm, (q << 1) + r);
        }
    }

    // gi preload for t=0
    float gir, giz, gin;
    {
        const float* gp = g_gi + u_gbl;
        gir = __ldg(gp); giz = __ldg(gp + HD); gin = __ldg(gp + 2 * HD);
    }

    int ph0 = 0, ph1 = 0;
    for (int t = 0; t < T_STEPS; t++) {
        const int cb = t & 1;          // current h buffer
        const int nb = cb ^ 1;         // buffer/barrier filled this step

        if (tid == 0) mbar_expect(smem_u32(&mbar[nb]), 2048u);

        // prefetch gi for t+1
        float girn, gizn, ginn;
        {
            int tn = (t + 1 < T_STEPS) ? t + 1 : t;
            const float* gp = g_gi + (size_t)tn * G3 + u_gbl;
            girn = __ldg(gp); gizn = __ldg(gp + HD); ginn = __ldg(gp + 2 * HD);
        }

        // load h chunk (32 floats) — transposed layout, conflict-free
        ull h2[16];
        {
            const longlong2* hp = (const longlong2*)(hT + (cb << 9));
#pragma unroll
            for (int j = 0; j < 8; j++) {
                longlong2 qv = hp[(j << 4) + c4];
                h2[2 * j]     = (ull)qv.x;
                h2[2 * j + 1] = (ull)qv.y;
            }
        }
        float hold = hT[(cb << 9) + hoffb];

        // matvec: 6 groups
        float accs[6];
#pragma unroll
        for (int g = 0; g < 5; g++) {
            ull a = 0ull;
#pragma unroll
            for (int k = 0; k < 16; k++) fma2(a, wreg[g][k], h2[k]);
            float2 u2 = upk2(a);
            accs[g] = u2.x + u2.y;
        }
        {
            ull a = 0ull;
            const longlong2* wp = (const longlong2*)&Wsh4[w][rh][0][c4];
#pragma unroll
            for (int j = 0; j < 8; j++) {
                longlong2 qv = wp[j << 4];
                fma2(a, (ull)qv.x, h2[2 * j]);
                fma2(a, (ull)qv.y, h2[2 * j + 1]);
            }
            float2 u2 = upk2(a);
            accs[5] = u2.x + u2.y;
        }

        // butterfly: replicate reduced sums across each 16-lane half
#pragma unroll
        for (int d = 8; d > 0; d >>= 1)
#pragma unroll
            for (int g = 0; g < 6; g++)
                accs[g] += __shfl_xor_sync(0xffffffffu, accs[g], d);

        // in-lane gather of this unit's (r, z, n) pre-activations
        const bool b0 = (lane & 1);
        float pr = b0 ? accs[1] : accs[0];
        float pz = b0 ? accs[3] : accs[2];
        float pn = b0 ? accs[5] : accs[4];

        float rg = fmaf(0.5f, tanh_fast(0.5f * (gir + pr + br)), 0.5f);
        float zg = fmaf(0.5f, tanh_fast(0.5f * (giz + pz + bz)), 0.5f);
        float ng = tanh_fast(fmaf(rg, pn + bn, gin));
        float hnew = fmaf(zg, hold - ng, ng);

        if (q == 0) g_hs[(size_t)t * HD + u_gbl] = hnew;

        unsigned hv = __float_as_uint(hnew);
        st_async_pre(rdata[nb][0], rbar[nb][0], hv);
        st_async_pre(rdata[nb][1], rbar[nb][1], hv);

        gir = girn; giz = gizn; gin = ginn;

        // wait for all 2048 bytes of h_{t+1}
        unsigned par = nb ? (unsigned)ph1 : (unsigned)ph0;
        mbar_wait(smem_u32(&mbar[nb]), par);
        if (nb) ph1 ^= 1; else ph0 ^= 1;
    }
    cluster_sync_all();   // don't exit while peers may still touch our smem
}

// ---------------------------------------------------------------------------
// Attention pooling
// ---------------------------------------------------------------------------
__global__ void __launch_bounds__(128)
att_logits_kernel(const float* __restrict__ watt)
{
    int w = blockIdx.x * 4 + (threadIdx.x >> 5);
    int lane = threadIdx.x & 31;
    for (int i = 0; i < 8; i++) {
        int t = w * 8 + i;
        const float* hp = g_hs + (size_t)t * HD;
        float acc = 0.f;
#pragma unroll
        for (int k = 0; k < 16; k++)
            acc += hp[lane + (k << 5)] * watt[lane + (k << 5)];
        acc += __shfl_xor_sync(0xffffffffu, acc, 16);
        acc += __shfl_xor_sync(0xffffffffu, acc, 8);
        acc += __shfl_xor_sync(0xffffffffu, acc, 4);
        acc += __shfl_xor_sync(0xffffffffu, acc, 2);
        acc += __shfl_xor_sync(0xffffffffu, acc, 1);
        if (lane == 0) g_logits[t] = acc;
    }
}

__global__ void __launch_bounds__(1024)
att_softmax_kernel()
{
    __shared__ float red[1024];
    int tid = threadIdx.x;
    float l[4];
    float mx = -1e30f;
#pragma unroll
    for (int i = 0; i < 4; i++) {
        l[i] = g_logits[tid + (i << 10)];
        mx = fmaxf(mx, l[i]);
    }
    red[tid] = mx;
    __syncthreads();
    for (int s = 512; s > 0; s >>= 1) {
        if (tid < s) red[tid] = fmaxf(red[tid], red[tid + s]);
        __syncthreads();
    }
    mx = red[0];
    __syncthreads();
    float e[4];
    float se = 0.f;
#pragma unroll
    for (int i = 0; i < 4; i++) {
        e[i] = __expf(l[i] - mx);
        se += e[i];
    }
    red[tid] = se;
    __syncthreads();
    for (int s = 512; s > 0; s >>= 1) {
        if (tid < s) red[tid] += red[tid + s];
        __syncthreads();
    }
    float inv = 1.0f / red[0];
#pragma unroll
    for (int i = 0; i < 4; i++)
        g_alpha[tid + (i << 10)] = e[i] * inv;
}

__global__ void __launch_bounds__(512)
att_out_kernel()
{
    int b = blockIdx.x;
    int d = threadIdx.x;
    float acc = 0.f;
    for (int i = 0; i < 128; i++) {
        int t = b * 128 + i;
        acc += g_alpha[t] * g_hs[(size_t)t * HD + d];
    }
    g_part[b * HD + d] = acc;
}

__global__ void __launch_bounds__(512)
att_final_kernel(float* __restrict__ out)
{
    int d = threadIdx.x;
    float acc = 0.f;
#pragma unroll
    for (int b = 0; b < 32; b++)
        acc += g_part[b * HD + d];
    out[d] = acc;
}

// ---------------------------------------------------------------------------
// Launch
// ---------------------------------------------------------------------------
extern "C" void kernel_launch(void* const* d_in, const int* in_sizes, int n_in,
                              void* d_out, int out_size)
{
    const float* H    = (const float*)d_in[0];
    // d_in[1] = TE (unused by reference)
    const float* X    = (const float*)d_in[2];
    const float* Wih  = (const float*)d_in[3];
    const float* Whh  = (const float*)d_in[4];
    const float* bih  = (const float*)d_in[5];
    const float* bhh  = (const float*)d_in[6];
    const float* watt = (const float*)d_in[7];
    float* out = (float*)d_out;

    gemm1_kernel<<<dim3(32, 8), 256>>>(H, X);
    gemm2_kernel<<<dim3(32, 24), 256>>>(Wih, bih);

    cudaFuncSetAttribute(scan_kernel,
                         cudaFuncAttributeNonPortableClusterSizeAllowed, 1);

    cudaLaunchConfig_t cfg = {};
    cfg.gridDim = dim3(16, 1, 1);
    cfg.blockDim = dim3(SCAN_THREADS, 1, 1);
    cfg.dynamicSmemBytes = 0;
    cfg.stream = 0;
    cudaLaunchAttribute attr[1];
    attr[0].id = cudaLaunchAttributeClusterDimension;
    attr[0].val.clusterDim.x = 16;
    attr[0].val.clusterDim.y = 1;
    attr[0].val.clusterDim.z = 1;
    cfg.attrs = attr;
    cfg.numAttrs = 1;
    cudaLaunchKernelEx(&cfg, scan_kernel, Whh, bhh);

    att_logits_kernel<<<128, 128>>>(watt);
    att_softmax_kernel<<<1, 1024>>>();
    att_out_kernel<<<32, 512>>>();
    att_final_kernel<<<1, 512>>>(out);
}